// round 2
// baseline (speedup 1.0000x reference)
#include <cuda_runtime.h>
#include <math.h>

#define NN 100000
#define EE 1600000
#define C 64
#define RS 68            // padded smem row stride (floats)
#define TILE 128         // edges/nodes per CTA tile

// ---------------- device scratch (static, allocation-free) ----------------
__device__ float g_asrc[NN * C];
__device__ float g_adst[NN * C];
__device__ float g_v[NN * C];
__device__ float g_num[NN * C];
__device__ float g_den[NN * C];

// ---------------- helpers ----------------
__device__ __forceinline__ void red_add4(float* p, float4 v) {
    asm volatile("red.global.add.v4.f32 [%0], {%1,%2,%3,%4};"
                 :: "l"(p), "f"(v.x), "f"(v.y), "f"(v.z), "f"(v.w)
                 : "memory");
}
__device__ __forceinline__ float4 f4fma(float s, float4 w, float4 a) {
    a.x = fmaf(s, w.x, a.x); a.y = fmaf(s, w.y, a.y);
    a.z = fmaf(s, w.z, a.z); a.w = fmaf(s, w.w, a.w);
    return a;
}
__device__ __forceinline__ float4 f4relu(float4 a) {
    a.x = fmaxf(a.x, 0.f); a.y = fmaxf(a.y, 0.f);
    a.z = fmaxf(a.z, 0.f); a.w = fmaxf(a.w, 0.f);
    return a;
}

// ---------------- init ----------------
__global__ void zero_kernel() {
    int i = blockIdx.x * blockDim.x + threadIdx.x;
    int stride = gridDim.x * blockDim.x;
    float4 z = make_float4(0.f, 0.f, 0.f, 0.f);
    for (; i < NN * C / 4; i += stride) {
        ((float4*)g_num)[i] = z;
        ((float4*)g_den)[i] = z;
    }
}

// ============================================================================
// node_prep: h = relu(x@W_in+b); asrc/adst/v = h@{W_src,W_dst,W_lin}
// 256 threads; thread -> (2 nodes, 16 channels). Register-blocked GEMM.
// ============================================================================
__global__ void __launch_bounds__(256) node_prep(
    const float* __restrict__ x,
    const float* __restrict__ W_in, const float* __restrict__ b_in,
    const float* __restrict__ W_lin, const float* __restrict__ W_src,
    const float* __restrict__ W_dst)
{
    extern __shared__ float sm[];
    float* sWin = sm;            // 4096
    float* sbin = sm + 4096;     // 64
    float* sWs  = sm + 4160;     // 4096
    float* sWd  = sm + 8256;     // 4096
    float* sWl  = sm + 12352;    // 4096
    float* bufA = sm + 16448;    // 128*68
    float* bufB = sm + 25152;    // 128*68  (total 33856 floats)

    int t = threadIdx.x;
    for (int i = t; i < 4096; i += 256) {
        sWin[i] = W_in[i];  sWs[i] = W_src[i];
        sWd[i]  = W_dst[i]; sWl[i] = W_lin[i];
    }
    if (t < 64) sbin[t] = b_in[t];
    __syncthreads();

    int cg = t & 3, c0 = cg * 16;
    int r0 = (t >> 2) * 2;          // local node rows (2 per thread)
    int ntiles = (NN + TILE - 1) / TILE;

    for (int tile = blockIdx.x; tile < ntiles; tile += gridDim.x) {
        int base = tile * TILE;
        // stage x tile (coalesced)
#pragma unroll
        for (int r = 0; r < 8; r++) {
            int i = t + 256 * r;           // float4 index in tile
            int row = i >> 4, col = (i & 15) * 4;
            int n = base + row;
            if (n < NN)
                *(float4*)&bufA[row * RS + col] = *(const float4*)&x[(size_t)n * 64 + col];
        }
        __syncthreads();

        // layer 1: h = relu(x@W_in+b) -> bufB
        {
            float4 acc[2][4];
#pragma unroll
            for (int i = 0; i < 2; i++)
#pragma unroll
                for (int j = 0; j < 4; j++) acc[i][j] = *(float4*)&sbin[c0 + 4 * j];
#pragma unroll 8
            for (int k = 0; k < 64; k++) {
                float a0 = bufA[r0 * RS + k];
                float a1 = bufA[(r0 + 1) * RS + k];
#pragma unroll
                for (int j = 0; j < 4; j++) {
                    float4 w = *(float4*)&sWin[k * 64 + c0 + 4 * j];
                    acc[0][j] = f4fma(a0, w, acc[0][j]);
                    acc[1][j] = f4fma(a1, w, acc[1][j]);
                }
            }
#pragma unroll
            for (int i = 0; i < 2; i++)
#pragma unroll
                for (int j = 0; j < 4; j++)
                    *(float4*)&bufB[(r0 + i) * RS + c0 + 4 * j] = f4relu(acc[i][j]);
        }
        __syncthreads();

        // fused three output GEMMs from bufB
        {
            float4 aS[2][4], aD[2][4], aL[2][4];
#pragma unroll
            for (int i = 0; i < 2; i++)
#pragma unroll
                for (int j = 0; j < 4; j++) {
                    aS[i][j] = make_float4(0, 0, 0, 0);
                    aD[i][j] = make_float4(0, 0, 0, 0);
                    aL[i][j] = make_float4(0, 0, 0, 0);
                }
#pragma unroll 4
            for (int k = 0; k < 64; k++) {
                float a0 = bufB[r0 * RS + k];
                float a1 = bufB[(r0 + 1) * RS + k];
#pragma unroll
                for (int j = 0; j < 4; j++) {
                    float4 wS = *(float4*)&sWs[k * 64 + c0 + 4 * j];
                    float4 wD = *(float4*)&sWd[k * 64 + c0 + 4 * j];
                    float4 wL = *(float4*)&sWl[k * 64 + c0 + 4 * j];
                    aS[0][j] = f4fma(a0, wS, aS[0][j]); aS[1][j] = f4fma(a1, wS, aS[1][j]);
                    aD[0][j] = f4fma(a0, wD, aD[0][j]); aD[1][j] = f4fma(a1, wD, aD[1][j]);
                    aL[0][j] = f4fma(a0, wL, aL[0][j]); aL[1][j] = f4fma(a1, wL, aL[1][j]);
                }
            }
#pragma unroll
            for (int i = 0; i < 2; i++) {
                int n = base + r0 + i;
                if (n < NN) {
#pragma unroll
                    for (int j = 0; j < 4; j++) {
                        *(float4*)&g_asrc[(size_t)n * 64 + c0 + 4 * j] = aS[i][j];
                        *(float4*)&g_adst[(size_t)n * 64 + c0 + 4 * j] = aD[i][j];
                        *(float4*)&g_v[(size_t)n * 64 + c0 + 4 * j]    = aL[i][j];
                    }
                }
            }
        }
        __syncthreads();
    }
}

// ============================================================================
// edge kernel: pos-MLP + attn-MLP + softmax-accumulate, register-blocked
// 256 threads; thread -> (2 edges, 16 channels)
// ============================================================================
__global__ void __launch_bounds__(256) edge_kernel(
    const float* __restrict__ pos,
    const int* __restrict__ src, const int* __restrict__ dst,
    const float* __restrict__ posw1, const float* __restrict__ posb1,
    const float* __restrict__ posw2, const float* __restrict__ posb2,
    const float* __restrict__ attw1, const float* __restrict__ attb1,
    const float* __restrict__ attw2, const float* __restrict__ attb2)
{
    extern __shared__ float sm[];
    float* sw1  = sm;              // 192
    float* sb1  = sm + 192;
    float* sb2  = sm + 256;
    float* sab1 = sm + 320;
    float* sab2 = sm + 384;
    float* sw2  = sm + 448;        // 4096
    float* sa1  = sm + 4544;       // 4096
    float* sa2  = sm + 8640;       // 4096
    float* dpos = sm + 12736;      // 384
    float* bufA = sm + 13120;      // 128*68
    float* bufB = sm + 21824;      // 128*68
    int*   sidx = (int*)(sm + 30528); // 128
    int*   didx = (int*)(sm + 30656); // 128 (total 30784 floats)

    int t = threadIdx.x;
    for (int i = t; i < 4096; i += 256) {
        sw2[i] = posw2[i]; sa1[i] = attw1[i]; sa2[i] = attw2[i];
    }
    if (t < 192) sw1[t] = posw1[t];
    if (t < 64) { sb1[t] = posb1[t]; sb2[t] = posb2[t];
                  sab1[t] = attb1[t]; sab2[t] = attb2[t]; }
    __syncthreads();

    int cg = t & 3, c0 = cg * 16;
    int e0 = (t >> 2) * 2;          // local edge rows (2 per thread)
    const int ntiles = EE / TILE;   // 12500 exactly

    for (int tile = blockIdx.x; tile < ntiles; tile += gridDim.x) {
        // stage indices + pos deltas
        if (t < TILE) {
            int e = tile * TILE + t;
            int s = src[e], d = dst[e];
            sidx[t] = s; didx[t] = d;
            dpos[t * 3 + 0] = pos[d * 3 + 0] - pos[s * 3 + 0];
            dpos[t * 3 + 1] = pos[d * 3 + 1] - pos[s * 3 + 1];
            dpos[t * 3 + 2] = pos[d * 3 + 2] - pos[s * 3 + 2];
        }
        __syncthreads();

        // layer 1 (pos MLP first layer, K=3): h1 -> bufA
#pragma unroll
        for (int i = 0; i < 2; i++) {
            int e = e0 + i;
            float p0 = dpos[e * 3 + 0], p1 = dpos[e * 3 + 1], p2 = dpos[e * 3 + 2];
#pragma unroll
            for (int j = 0; j < 4; j++) {
                float4 acc = *(float4*)&sb1[c0 + 4 * j];
                acc = f4fma(p0, *(float4*)&sw1[0 * 64 + c0 + 4 * j], acc);
                acc = f4fma(p1, *(float4*)&sw1[1 * 64 + c0 + 4 * j], acc);
                acc = f4fma(p2, *(float4*)&sw1[2 * 64 + c0 + 4 * j], acc);
                *(float4*)&bufA[e * RS + c0 + 4 * j] = f4relu(acc);
            }
        }
        __syncthreads();

        // layer 2: delta = relu(h1@posW2+b2), kept in registers; t -> bufB
        float4 del[2][4];
        {
            float4 acc[2][4];
#pragma unroll
            for (int i = 0; i < 2; i++)
#pragma unroll
                for (int j = 0; j < 4; j++) acc[i][j] = *(float4*)&sb2[c0 + 4 * j];
#pragma unroll 8
            for (int k = 0; k < 64; k++) {
                float a0 = bufA[e0 * RS + k];
                float a1 = bufA[(e0 + 1) * RS + k];
#pragma unroll
                for (int j = 0; j < 4; j++) {
                    float4 w = *(float4*)&sw2[k * 64 + c0 + 4 * j];
                    acc[0][j] = f4fma(a0, w, acc[0][j]);
                    acc[1][j] = f4fma(a1, w, acc[1][j]);
                }
            }
#pragma unroll
            for (int i = 0; i < 2; i++) {
                int e = e0 + i;
                int s = sidx[e], d = didx[e];
                const float4* ad = (const float4*)&g_adst[(size_t)d * 64 + c0];
                const float4* as = (const float4*)&g_asrc[(size_t)s * 64 + c0];
#pragma unroll
                for (int j = 0; j < 4; j++) {
                    float4 D = f4relu(acc[i][j]);
                    del[i][j] = D;
                    float4 A = ad[j], S = as[j], tv;
                    tv.x = A.x - S.x + D.x; tv.y = A.y - S.y + D.y;
                    tv.z = A.z - S.z + D.z; tv.w = A.w - S.w + D.w;
                    *(float4*)&bufB[e * RS + c0 + 4 * j] = tv;
                }
            }
        }
        __syncthreads();

        // layer 3: h2 = relu(t@attW1+b1) -> bufA
        {
            float4 acc[2][4];
#pragma unroll
            for (int i = 0; i < 2; i++)
#pragma unroll
                for (int j = 0; j < 4; j++) acc[i][j] = *(float4*)&sab1[c0 + 4 * j];
#pragma unroll 8
            for (int k = 0; k < 64; k++) {
                float a0 = bufB[e0 * RS + k];
                float a1 = bufB[(e0 + 1) * RS + k];
#pragma unroll
                for (int j = 0; j < 4; j++) {
                    float4 w = *(float4*)&sa1[k * 64 + c0 + 4 * j];
                    acc[0][j] = f4fma(a0, w, acc[0][j]);
                    acc[1][j] = f4fma(a1, w, acc[1][j]);
                }
            }
#pragma unroll
            for (int i = 0; i < 2; i++)
#pragma unroll
                for (int j = 0; j < 4; j++)
                    *(float4*)&bufA[(e0 + i) * RS + c0 + 4 * j] = f4relu(acc[i][j]);
        }
        __syncthreads();

        // layer 4: a = relu(h2@attW2+b2); exp; accumulate
        {
            float4 acc[2][4];
#pragma unroll
            for (int i = 0; i < 2; i++)
#pragma unroll
                for (int j = 0; j < 4; j++) acc[i][j] = *(float4*)&sab2[c0 + 4 * j];
#pragma unroll 8
            for (int k = 0; k < 64; k++) {
                float a0 = bufA[e0 * RS + k];
                float a1 = bufA[(e0 + 1) * RS + k];
#pragma unroll
                for (int j = 0; j < 4; j++) {
                    float4 w = *(float4*)&sa2[k * 64 + c0 + 4 * j];
                    acc[0][j] = f4fma(a0, w, acc[0][j]);
                    acc[1][j] = f4fma(a1, w, acc[1][j]);
                }
            }
#pragma unroll
            for (int i = 0; i < 2; i++) {
                int e = e0 + i;
                int s = sidx[e], d = didx[e];
                float* nump = &g_num[(size_t)d * 64 + c0];
                float* denp = &g_den[(size_t)d * 64 + c0];
                const float4* vv = (const float4*)&g_v[(size_t)s * 64 + c0];
#pragma unroll
                for (int j = 0; j < 4; j++) {
                    float4 a = f4relu(acc[i][j]);
                    float4 ex;
                    ex.x = __expf(a.x); ex.y = __expf(a.y);
                    ex.z = __expf(a.z); ex.w = __expf(a.w);
                    float4 V = vv[j], D = del[i][j], m;
                    m.x = ex.x * (V.x + D.x); m.y = ex.y * (V.y + D.y);
                    m.z = ex.z * (V.z + D.z); m.w = ex.w * (V.w + D.w);
                    red_add4(nump + 4 * j, m);
                    red_add4(denp + 4 * j, ex);
                }
            }
        }
        __syncthreads();
    }
}

// ============================================================================
// final: out = relu((num/den)@W_out + b_out)
// ============================================================================
__global__ void __launch_bounds__(256) final_kernel(
    const float* __restrict__ W_out, const float* __restrict__ b_out,
    float* __restrict__ out)
{
    extern __shared__ float sm[];
    float* sW  = sm;           // 4096
    float* sb  = sm + 4096;    // 64
    float* buf = sm + 4160;    // 128*68  (total 12864 floats)

    int t = threadIdx.x;
    for (int i = t; i < 4096; i += 256) sW[i] = W_out[i];
    if (t < 64) sb[t] = b_out[t];
    __syncthreads();

    int cg = t & 3, c0 = cg * 16;
    int r0 = (t >> 2) * 2;
    int ntiles = (NN + TILE - 1) / TILE;

    for (int tile = blockIdx.x; tile < ntiles; tile += gridDim.x) {
        int base = tile * TILE;
#pragma unroll
        for (int r = 0; r < 8; r++) {
            int i = t + 256 * r;
            int row = i >> 4, col = (i & 15) * 4;
            int n = base + row;
            if (n < NN) {
                float4 nu = *(const float4*)&g_num[(size_t)n * 64 + col];
                float4 de = *(const float4*)&g_den[(size_t)n * 64 + col];
                float4 rr;
                rr.x = nu.x / (de.x + 1e-16f); rr.y = nu.y / (de.y + 1e-16f);
                rr.z = nu.z / (de.z + 1e-16f); rr.w = nu.w / (de.w + 1e-16f);
                *(float4*)&buf[row * RS + col] = rr;
            }
        }
        __syncthreads();

        float4 acc[2][4];
#pragma unroll
        for (int i = 0; i < 2; i++)
#pragma unroll
            for (int j = 0; j < 4; j++) acc[i][j] = *(float4*)&sb[c0 + 4 * j];
#pragma unroll 8
        for (int k = 0; k < 64; k++) {
            float a0 = buf[r0 * RS + k];
            float a1 = buf[(r0 + 1) * RS + k];
#pragma unroll
            for (int j = 0; j < 4; j++) {
                float4 w = *(float4*)&sW[k * 64 + c0 + 4 * j];
                acc[0][j] = f4fma(a0, w, acc[0][j]);
                acc[1][j] = f4fma(a1, w, acc[1][j]);
            }
        }
#pragma unroll
        for (int i = 0; i < 2; i++) {
            int n = base + r0 + i;
            if (n < NN) {
#pragma unroll
                for (int j = 0; j < 4; j++)
                    *(float4*)&out[(size_t)n * 64 + c0 + 4 * j] = f4relu(acc[i][j]);
            }
        }
        __syncthreads();
    }
}

// ---------------- launch ----------------
extern "C" void kernel_launch(void* const* d_in, const int* in_sizes, int n_in,
                              void* d_out, int out_size)
{
    const float* x      = (const float*)d_in[0];
    const float* pos    = (const float*)d_in[1];
    const int*   ei     = (const int*)d_in[2];
    const float* W_in   = (const float*)d_in[3];
    const float* b_in   = (const float*)d_in[4];
    const float* W_out  = (const float*)d_in[5];
    const float* b_out  = (const float*)d_in[6];
    const float* W_lin  = (const float*)d_in[7];
    const float* W_src  = (const float*)d_in[8];
    const float* W_dst  = (const float*)d_in[9];
    const float* posw1  = (const float*)d_in[10];
    const float* posb1  = (const float*)d_in[11];
    const float* posw2  = (const float*)d_in[12];
    const float* posb2  = (const float*)d_in[13];
    const float* attw1  = (const float*)d_in[14];
    const float* attb1  = (const float*)d_in[15];
    const float* attw2  = (const float*)d_in[16];
    const float* attb2  = (const float*)d_in[17];
    float* out = (float*)d_out;

    const int NP_SMEM = 33856 * 4;
    const int EK_SMEM = 30784 * 4;
    const int FN_SMEM = 12864 * 4;
    cudaFuncSetAttribute(node_prep, cudaFuncAttributeMaxDynamicSharedMemorySize, NP_SMEM);
    cudaFuncSetAttribute(edge_kernel, cudaFuncAttributeMaxDynamicSharedMemorySize, EK_SMEM);
    cudaFuncSetAttribute(final_kernel, cudaFuncAttributeMaxDynamicSharedMemorySize, FN_SMEM);

    zero_kernel<<<1024, 256>>>();
    node_prep<<<148, 256, NP_SMEM>>>(x, W_in, b_in, W_lin, W_src, W_dst);
    edge_kernel<<<148, 256, EK_SMEM>>>(pos, ei, ei + EE,
                                       posw1, posb1, posw2, posb2,
                                       attw1, attb1, attw2, attb2);
    final_kernel<<<148, 256, FN_SMEM>>>(W_out, b_out, out);
}

// round 3
// speedup vs baseline: 2.8207x; 2.8207x over previous
#include <cuda_runtime.h>
#include <cstdint>
#include <math.h>

#define NN 100000
#define EE 1600000
#define RS 68              // padded smem row stride (floats): bank-conflict-free frags

// ---------------- device scratch ----------------
__device__ float g_asrc[NN * 64];
__device__ float g_adst[NN * 64];
__device__ float g_v[NN * 64];
__device__ float g_num[NN * 64];
__device__ float g_den[NN * 64];

// ---------------- helpers ----------------
__device__ __forceinline__ void red_add4(float* p, float4 v) {
    asm volatile("red.global.add.v4.f32 [%0], {%1,%2,%3,%4};"
                 :: "l"(p), "f"(v.x), "f"(v.y), "f"(v.z), "f"(v.w) : "memory");
}
__device__ __forceinline__ float to_tf32(float x) {
    unsigned u;
    asm("cvt.rna.tf32.f32 %0, %1;" : "=r"(u) : "f"(x));
    return __uint_as_float(u);
}
__device__ __forceinline__ void mma_tf32(float c[4], unsigned a0, unsigned a1,
                                         unsigned a2, unsigned a3,
                                         unsigned b0, unsigned b1) {
    asm volatile(
        "mma.sync.aligned.m16n8k8.row.col.f32.tf32.tf32.f32 "
        "{%0,%1,%2,%3},{%4,%5,%6,%7},{%8,%9},{%0,%1,%2,%3};"
        : "+f"(c[0]), "+f"(c[1]), "+f"(c[2]), "+f"(c[3])
        : "r"(a0), "r"(a1), "r"(a2), "r"(a3), "r"(b0), "r"(b1));
}

// GEMM: out[16 rows @ rbase][NT*8 cols @ n0base] += bufIn[128xRS] @ WT(tf32)
// WT layout: WT[n*RS + k]. Conflict-free for RS=68.
template<int NT>
__device__ __forceinline__ void gemm_tile(const float* __restrict__ bufIn,
                                          const float* __restrict__ WT,
                                          int rbase, int n0base, int lane,
                                          float acc[NT][4]) {
    int r = lane >> 2, c = lane & 3;
    const float* a0p = bufIn + (rbase + r) * RS + c;
    const float* a1p = a0p + 8 * RS;
#pragma unroll
    for (int k0 = 0; k0 < 64; k0 += 8) {
        unsigned a0 = __float_as_uint(a0p[k0]);
        unsigned a1 = __float_as_uint(a1p[k0]);
        unsigned a2 = __float_as_uint(a0p[k0 + 4]);
        unsigned a3 = __float_as_uint(a1p[k0 + 4]);
#pragma unroll
        for (int nt = 0; nt < NT; nt++) {
            const float* bp = WT + (size_t)(n0base + nt * 8 + r) * RS + k0 + c;
            unsigned b0 = __float_as_uint(bp[0]);
            unsigned b1 = __float_as_uint(bp[4]);
            mma_tf32(acc[nt], a0, a1, a2, a3, b0, b1);
        }
    }
}

template<int NT>
__device__ __forceinline__ void zero_acc(float acc[NT][4]) {
#pragma unroll
    for (int nt = 0; nt < NT; nt++)
#pragma unroll
        for (int j = 0; j < 4; j++) acc[nt][j] = 0.f;
}

// store frags to smem with bias+relu, optional tf32 round or exp
template<int NT, int MODE>   // MODE 0: tf32(relu(+b)); MODE 1: exp(relu(+b))
__device__ __forceinline__ void frag_store(float* __restrict__ bufOut,
                                           const float* __restrict__ bias,
                                           int rbase, int n0base, int lane,
                                           float acc[NT][4]) {
    int r0 = rbase + (lane >> 2);
#pragma unroll
    for (int nt = 0; nt < NT; nt++) {
        int col = n0base + nt * 8 + 2 * (lane & 3);
        float2 b = *(const float2*)&bias[col];
        float v00 = fmaxf(acc[nt][0] + b.x, 0.f);
        float v01 = fmaxf(acc[nt][1] + b.y, 0.f);
        float v10 = fmaxf(acc[nt][2] + b.x, 0.f);
        float v11 = fmaxf(acc[nt][3] + b.y, 0.f);
        if (MODE == 0) {
            v00 = to_tf32(v00); v01 = to_tf32(v01);
            v10 = to_tf32(v10); v11 = to_tf32(v11);
        } else {
            v00 = __expf(v00); v01 = __expf(v01);
            v10 = __expf(v10); v11 = __expf(v11);
        }
        *(float2*)&bufOut[(size_t)r0 * RS + col] = make_float2(v00, v01);
        *(float2*)&bufOut[(size_t)(r0 + 8) * RS + col] = make_float2(v10, v11);
    }
}

// ---------------- init ----------------
__global__ void zero_kernel() {
    int i = blockIdx.x * blockDim.x + threadIdx.x;
    int stride = gridDim.x * blockDim.x;
    float4 z = make_float4(0.f, 0.f, 0.f, 0.f);
    for (; i < NN * 64 / 4; i += stride) {
        ((float4*)g_num)[i] = z;
        ((float4*)g_den)[i] = z;
    }
}

// ============================================================================
// node_prep (256 thr): h = relu(x@W_in+b); asrc/adst/v = h@{W_src,W_dst,W_lin}
// ============================================================================
__global__ void __launch_bounds__(256) node_prep(
    const float* __restrict__ x,
    const float* __restrict__ W_in, const float* __restrict__ b_in,
    const float* __restrict__ W_lin, const float* __restrict__ W_src,
    const float* __restrict__ W_dst)
{
    extern __shared__ float sm[];
    float* WinT = sm;              // 4352
    float* WsT  = sm + 4352;
    float* WdT  = sm + 8704;
    float* WlT  = sm + 13056;
    float* bin  = sm + 17408;      // 64
    float* bufA = sm + 17472;      // 8704
    float* bufB = sm + 26176;      // 8704  -> total 34880 floats

    int t = threadIdx.x;
    for (int i = t; i < 4096; i += 256) {
        int k = i >> 6, n = i & 63;
        WinT[n * RS + k] = to_tf32(W_in[i]);
        WsT[n * RS + k]  = to_tf32(W_src[i]);
        WdT[n * RS + k]  = to_tf32(W_dst[i]);
        WlT[n * RS + k]  = to_tf32(W_lin[i]);
    }
    if (t < 64) bin[t] = b_in[t];
    __syncthreads();

    int w = t >> 5, lane = t & 31;
    int rbase = w * 16;
    int ntiles = (NN + 127) / 128;

    for (int tile = blockIdx.x; tile < ntiles; tile += gridDim.x) {
        int base = tile * 128;
        __syncthreads();   // protect bufA/bufB reuse
        // stage x (tf32-rounded), zero-fill tail rows
#pragma unroll
        for (int rr = 0; rr < 8; rr++) {
            int i = t + 256 * rr;
            int row = i >> 4, col = (i & 15) * 4;
            int n = base + row;
            float4 v = make_float4(0, 0, 0, 0);
            if (n < NN) {
                v = *(const float4*)&x[(size_t)n * 64 + col];
                v.x = to_tf32(v.x); v.y = to_tf32(v.y);
                v.z = to_tf32(v.z); v.w = to_tf32(v.w);
            }
            *(float4*)&bufA[(size_t)row * RS + col] = v;
        }
        __syncthreads();

        // h = relu(x@W_in + b) -> bufB (tf32)
        {
            float acc[8][4];
            zero_acc<8>(acc);
            gemm_tile<8>(bufA, WinT, rbase, 0, lane, acc);
            frag_store<8, 0>(bufB, bin, rbase, 0, lane, acc);
        }
        __syncthreads();

        // three output GEMMs, direct global store (fp32, no bias/relu)
        const float* WTs[3] = {WsT, WdT, WlT};
        float* outs[3] = {g_asrc, g_adst, g_v};
#pragma unroll
        for (int p = 0; p < 3; p++) {
            float acc[8][4];
            zero_acc<8>(acc);
            gemm_tile<8>(bufB, WTs[p], rbase, 0, lane, acc);
            int n0r = base + rbase + (lane >> 2);
#pragma unroll
            for (int nt = 0; nt < 8; nt++) {
                int col = nt * 8 + 2 * (lane & 3);
                if (n0r < NN)
                    *(float2*)&outs[p][(size_t)n0r * 64 + col] =
                        make_float2(acc[nt][0], acc[nt][1]);
                if (n0r + 8 < NN)
                    *(float2*)&outs[p][(size_t)(n0r + 8) * 64 + col] =
                        make_float2(acc[nt][2], acc[nt][3]);
            }
        }
    }
}

// ============================================================================
// edge kernel (512 thr): pos-MLP + attn-MLP + softmax-accumulate
// ============================================================================
__global__ void __launch_bounds__(512) edge_kernel(
    const float* __restrict__ pos,
    const int* __restrict__ src, const int* __restrict__ dst,
    const float* __restrict__ posw1, const float* __restrict__ posb1,
    const float* __restrict__ posw2, const float* __restrict__ posb2,
    const float* __restrict__ attw1, const float* __restrict__ attb1,
    const float* __restrict__ attw2, const float* __restrict__ attb2)
{
    extern __shared__ float sm[];
    float* sw1  = sm;              // 192 (row-major 3x64)
    float* sb1  = sm + 192;        // 64
    float* sb2  = sm + 256;        // 64
    float* sab1 = sm + 320;        // 64
    float* sab2 = sm + 384;        // 64
    float* wp2T = sm + 448;        // 4352
    float* wa1T = sm + 4800;       // 4352
    float* wa2T = sm + 9152;       // 4352
    float* dpos = sm + 13504;      // 384
    float* bufA = sm + 13888;      // 8704
    float* bufB = sm + 22592;      // 8704
    float* bufD = sm + 31296;      // 8704
    int*   sidx = (int*)(sm + 40000);  // 128
    int*   didx = (int*)(sm + 40128);  // 128  -> total 40256 floats (157.25 KB)

    int t = threadIdx.x;
    for (int i = t; i < 4096; i += 512) {
        int k = i >> 6, n = i & 63;
        wp2T[n * RS + k] = to_tf32(posw2[i]);
        wa1T[n * RS + k] = to_tf32(attw1[i]);
        wa2T[n * RS + k] = to_tf32(attw2[i]);
    }
    if (t < 192) sw1[t] = posw1[t];
    if (t < 64) { sb1[t] = posb1[t]; sb2[t] = posb2[t];
                  sab1[t] = attb1[t]; sab2[t] = attb2[t]; }
    __syncthreads();

    int w = t >> 5, lane = t & 31;
    int rbase = (w & 7) * 16;        // 8 M-groups
    int n0base = (w >> 3) * 32;      // 2 N-halves
    int cg = t & 3, c0 = cg * 16;    // scalar-phase mapping
    int el = t >> 2;                 // local edge 0..127
    const int ntiles = EE / 128;     // 12500

    for (int tile = blockIdx.x; tile < ntiles; tile += gridDim.x) {
        __syncthreads();   // protect prior tile's buffers
        // ---- stage indices + pos deltas ----
        if (t < 128) {
            int e = tile * 128 + t;
            int s = src[e], d = dst[e];
            sidx[t] = s; didx[t] = d;
            dpos[t * 3 + 0] = pos[d * 3 + 0] - pos[s * 3 + 0];
            dpos[t * 3 + 1] = pos[d * 3 + 1] - pos[s * 3 + 1];
            dpos[t * 3 + 2] = pos[d * 3 + 2] - pos[s * 3 + 2];
        }
        __syncthreads();

        // ---- layer 1 (K=3, scalar): h1 -> bufA (tf32) ----
        {
            float p0 = dpos[el * 3 + 0], p1 = dpos[el * 3 + 1], p2 = dpos[el * 3 + 2];
#pragma unroll
            for (int j = 0; j < 4; j++) {
                int col = c0 + 4 * j;
                float4 b = *(float4*)&sb1[col];
                float4 w0 = *(float4*)&sw1[col];
                float4 w1r = *(float4*)&sw1[64 + col];
                float4 w2r = *(float4*)&sw1[128 + col];
                float4 a;
                a.x = fmaxf(fmaf(p2, w2r.x, fmaf(p1, w1r.x, fmaf(p0, w0.x, b.x))), 0.f);
                a.y = fmaxf(fmaf(p2, w2r.y, fmaf(p1, w1r.y, fmaf(p0, w0.y, b.y))), 0.f);
                a.z = fmaxf(fmaf(p2, w2r.z, fmaf(p1, w1r.z, fmaf(p0, w0.z, b.z))), 0.f);
                a.w = fmaxf(fmaf(p2, w2r.w, fmaf(p1, w1r.w, fmaf(p0, w0.w, b.w))), 0.f);
                a.x = to_tf32(a.x); a.y = to_tf32(a.y);
                a.z = to_tf32(a.z); a.w = to_tf32(a.w);
                *(float4*)&bufA[(size_t)el * RS + col] = a;
            }
        }
        __syncthreads();

        // ---- layer 2 (MMA): delta = relu(h1@posW2+b2) -> bufD (tf32) ----
        {
            float acc[4][4];
            zero_acc<4>(acc);
            gemm_tile<4>(bufA, wp2T, rbase, n0base, lane, acc);
            frag_store<4, 0>(bufD, sb2, rbase, n0base, lane, acc);
        }
        __syncthreads();

        // ---- gather: t = tf32(adst[d]-asrc[s]+delta) -> bufB ----
        {
            int s = sidx[el], d = didx[el];
            const float4* ad = (const float4*)&g_adst[(size_t)d * 64 + c0];
            const float4* as = (const float4*)&g_asrc[(size_t)s * 64 + c0];
#pragma unroll
            for (int j = 0; j < 4; j++) {
                float4 A = ad[j], S = as[j];
                float4 D = *(float4*)&bufD[(size_t)el * RS + c0 + 4 * j];
                float4 tv;
                tv.x = to_tf32(A.x - S.x + D.x);
                tv.y = to_tf32(A.y - S.y + D.y);
                tv.z = to_tf32(A.z - S.z + D.z);
                tv.w = to_tf32(A.w - S.w + D.w);
                *(float4*)&bufB[(size_t)el * RS + c0 + 4 * j] = tv;
            }
        }
        __syncthreads();

        // ---- layer 3 (MMA): h2 = relu(t@attW1+b1) -> bufA (tf32) ----
        {
            float acc[4][4];
            zero_acc<4>(acc);
            gemm_tile<4>(bufB, wa1T, rbase, n0base, lane, acc);
            frag_store<4, 0>(bufA, sab1, rbase, n0base, lane, acc);
        }
        __syncthreads();

        // ---- layer 4 (MMA): ex = exp(relu(h2@attW2+b2)) -> bufB (fp32) ----
        {
            float acc[4][4];
            zero_acc<4>(acc);
            gemm_tile<4>(bufA, wa2T, rbase, n0base, lane, acc);
            frag_store<4, 1>(bufB, sab2, rbase, n0base, lane, acc);
        }
        __syncthreads();

        // ---- scatter: num += ex*(v[s]+delta); den += ex ----
        {
            int s = sidx[el], d = didx[el];
            float* nump = &g_num[(size_t)d * 64 + c0];
            float* denp = &g_den[(size_t)d * 64 + c0];
            const float4* vv = (const float4*)&g_v[(size_t)s * 64 + c0];
#pragma unroll
            for (int j = 0; j < 4; j++) {
                float4 ex = *(float4*)&bufB[(size_t)el * RS + c0 + 4 * j];
                float4 D  = *(float4*)&bufD[(size_t)el * RS + c0 + 4 * j];
                float4 V  = vv[j];
                float4 m;
                m.x = ex.x * (V.x + D.x); m.y = ex.y * (V.y + D.y);
                m.z = ex.z * (V.z + D.z); m.w = ex.w * (V.w + D.w);
                red_add4(nump + 4 * j, m);
                red_add4(denp + 4 * j, ex);
            }
        }
    }
}

// ============================================================================
// final (256 thr): out = relu((num/den)@W_out + b_out)
// ============================================================================
__global__ void __launch_bounds__(256) final_kernel(
    const float* __restrict__ W_out, const float* __restrict__ b_out,
    float* __restrict__ out)
{
    extern __shared__ float sm[];
    float* WoT  = sm;              // 4352
    float* bo   = sm + 4352;       // 64
    float* bufA = sm + 4416;       // 8704 -> total 13120 floats

    int t = threadIdx.x;
    for (int i = t; i < 4096; i += 256) {
        int k = i >> 6, n = i & 63;
        WoT[n * RS + k] = to_tf32(W_out[i]);
    }
    if (t < 64) bo[t] = b_out[t];
    __syncthreads();

    int w = t >> 5, lane = t & 31;
    int rbase = w * 16;
    int ntiles = (NN + 127) / 128;

    for (int tile = blockIdx.x; tile < ntiles; tile += gridDim.x) {
        int base = tile * 128;
        __syncthreads();
        // stage ratio -> bufA (tf32)
#pragma unroll
        for (int rr = 0; rr < 8; rr++) {
            int i = t + 256 * rr;
            int row = i >> 4, col = (i & 15) * 4;
            int n = base + row;
            float4 v = make_float4(0, 0, 0, 0);
            if (n < NN) {
                float4 nu = *(const float4*)&g_num[(size_t)n * 64 + col];
                float4 de = *(const float4*)&g_den[(size_t)n * 64 + col];
                v.x = to_tf32(nu.x / (de.x + 1e-16f));
                v.y = to_tf32(nu.y / (de.y + 1e-16f));
                v.z = to_tf32(nu.z / (de.z + 1e-16f));
                v.w = to_tf32(nu.w / (de.w + 1e-16f));
            }
            *(float4*)&bufA[(size_t)row * RS + col] = v;
        }
        __syncthreads();

        float acc[8][4];
        zero_acc<8>(acc);
        gemm_tile<8>(bufA, WoT, rbase, 0, lane, acc);

        int n0r = base + rbase + (lane >> 2);
#pragma unroll
        for (int nt = 0; nt < 8; nt++) {
            int col = nt * 8 + 2 * (lane & 3);
            float2 b = *(const float2*)&bo[col];
            if (n0r < NN)
                *(float2*)&out[(size_t)n0r * 64 + col] =
                    make_float2(fmaxf(acc[nt][0] + b.x, 0.f),
                                fmaxf(acc[nt][1] + b.y, 0.f));
            if (n0r + 8 < NN)
                *(float2*)&out[(size_t)(n0r + 8) * 64 + col] =
                    make_float2(fmaxf(acc[nt][2] + b.x, 0.f),
                                fmaxf(acc[nt][3] + b.y, 0.f));
        }
    }
}

// ---------------- launch ----------------
extern "C" void kernel_launch(void* const* d_in, const int* in_sizes, int n_in,
                              void* d_out, int out_size)
{
    const float* x      = (const float*)d_in[0];
    const float* pos    = (const float*)d_in[1];
    const int*   ei     = (const int*)d_in[2];
    const float* W_in   = (const float*)d_in[3];
    const float* b_in   = (const float*)d_in[4];
    const float* W_out  = (const float*)d_in[5];
    const float* b_out  = (const float*)d_in[6];
    const float* W_lin  = (const float*)d_in[7];
    const float* W_src  = (const float*)d_in[8];
    const float* W_dst  = (const float*)d_in[9];
    const float* posw1  = (const float*)d_in[10];
    const float* posb1  = (const float*)d_in[11];
    const float* posw2  = (const float*)d_in[12];
    const float* posb2  = (const float*)d_in[13];
    const float* attw1  = (const float*)d_in[14];
    const float* attb1  = (const float*)d_in[15];
    const float* attw2  = (const float*)d_in[16];
    const float* attb2  = (const float*)d_in[17];
    float* out = (float*)d_out;

    const int NP_SMEM = 34880 * 4;
    const int EK_SMEM = 40256 * 4;
    const int FN_SMEM = 13120 * 4;
    cudaFuncSetAttribute(node_prep, cudaFuncAttributeMaxDynamicSharedMemorySize, NP_SMEM);
    cudaFuncSetAttribute(edge_kernel, cudaFuncAttributeMaxDynamicSharedMemorySize, EK_SMEM);
    cudaFuncSetAttribute(final_kernel, cudaFuncAttributeMaxDynamicSharedMemorySize, FN_SMEM);

    zero_kernel<<<1024, 256>>>();
    node_prep<<<148, 256, NP_SMEM>>>(x, W_in, b_in, W_lin, W_src, W_dst);
    edge_kernel<<<148, 512, EK_SMEM>>>(pos, ei, ei + EE,
                                       posw1, posb1, posw2, posb2,
                                       attw1, attb1, attw2, attb2);
    final_kernel<<<444, 256, FN_SMEM>>>(W_out, b_out, out);
}